// round 11
// baseline (speedup 1.0000x reference)
#include <cuda_runtime.h>
#include <cuda_bf16.h>
#include <cstdint>

// ---------------------------------------------------------------------------
// Problem constants
// ---------------------------------------------------------------------------
#define T_LEN   262144
#define B_N     16
#define W_LEN   8640
#define PAD     4320
#define F_META  8
#define NCHUNK  32

// GEMM decomposition
#define M_CTA   512
#define GRID_G  (T_LEN / M_CTA)   // 512 CTAs
#define JT      512               // taps per x chunk (32 k16-steps)
#define NCHK    18                // chunks (576 steps >= 544+28 band)
#define XSROW   528               // x smem pitch elems; 528 % 64 == 16 -> conflict-free LDS.64
#define WBUF    9792              // guarded weight buffer elems
#define WOFF    512
#define XPITCH  271872            // gxp row pitch elems (mult of 16)

// smem byte offsets
#define WH_OFF   0
#define WL_OFF   19584
#define XS_OFF   39168            // 2 buffers x (2 planes x 16896B) = 67584
#define XPLANE   16896            // 16 rows x 528 elems x 2B
#define XBUF     33792            // both planes
#define SMEM_SZ  106752

// ---------------------------------------------------------------------------
// Device scratch (no cudaMalloc allowed)
// ---------------------------------------------------------------------------
__device__ float g_w[W_LEN];
__device__ __align__(16) unsigned short g_wh[WBUF];
__device__ __align__(16) unsigned short g_wl[WBUF];
__device__ __align__(16) unsigned short gxph[B_N * XPITCH];   // frag-packed
__device__ __align__(16) unsigned short gxpl[B_N * XPITCH];
__device__ float g_partial[B_N * NCHUNK];
__device__ float g_scale[B_N];

// ---------------------------------------------------------------------------
// Helpers
// ---------------------------------------------------------------------------
__device__ __forceinline__ uint32_t pk(const unsigned short* p) {
    return (uint32_t)p[0] | ((uint32_t)p[1] << 16);
}
__device__ __forceinline__ void mma16816(float* d, uint32_t a0, uint32_t a1,
                                         uint32_t a2, uint32_t a3,
                                         uint32_t b0, uint32_t b1) {
    asm volatile(
        "mma.sync.aligned.m16n8k16.row.col.f32.bf16.bf16.f32 "
        "{%0,%1,%2,%3}, {%4,%5,%6,%7}, {%8,%9}, {%0,%1,%2,%3};"
        : "+f"(d[0]), "+f"(d[1]), "+f"(d[2]), "+f"(d[3])
        : "r"(a0), "r"(a1), "r"(a2), "r"(a3), "r"(b0), "r"(b1));
}
__device__ __forceinline__ void cp16(uint32_t dst, const void* src) {
    asm volatile("cp.async.cg.shared.global [%0], [%1], 16;"
                 :: "r"(dst), "l"(src) : "memory");
}

// ---------------------------------------------------------------------------
// Prep 1: softmax over temporal_weights, flipped -> g_w
// ---------------------------------------------------------------------------
__global__ void softmax_flip_kernel(const float* __restrict__ tw) {
    __shared__ float red[256];
    __shared__ float s_max, s_invsum;
    const int tid = threadIdx.x;

    float m = -1e30f;
    for (int i = tid; i < W_LEN; i += 256) m = fmaxf(m, tw[i]);
    red[tid] = m; __syncthreads();
    for (int s = 128; s > 0; s >>= 1) {
        if (tid < s) red[tid] = fmaxf(red[tid], red[tid + s]);
        __syncthreads();
    }
    if (tid == 0) s_max = red[0];
    __syncthreads();
    const float mx = s_max;
    __syncthreads();

    float sum = 0.f;
    for (int i = tid; i < W_LEN; i += 256) sum += expf(tw[i] - mx);
    red[tid] = sum; __syncthreads();
    for (int s = 128; s > 0; s >>= 1) {
        if (tid < s) red[tid] += red[tid + s];
        __syncthreads();
    }
    if (tid == 0) s_invsum = 1.f / red[0];
    __syncthreads();
    const float inv = s_invsum;

    for (int i = tid; i < W_LEN; i += 256)
        g_w[W_LEN - 1 - i] = expf(tw[i] - mx) * inv;
}

// ---------------------------------------------------------------------------
// Prep 2: guarded split-bf16 weight buffer
// ---------------------------------------------------------------------------
__global__ void wsplit_kernel() {
    for (int i = threadIdx.x; i < WBUF; i += 256) {
        int wi = i - WOFF;
        float v = (wi >= 0 && wi < W_LEN) ? g_w[wi] : 0.f;
        __nv_bfloat16 h = __float2bfloat16(v);
        float lo = v - __bfloat162float(h);
        __nv_bfloat16 l = __float2bfloat16(lo);
        g_wh[i] = __bfloat16_as_ushort(h);
        g_wl[i] = __bfloat16_as_ushort(l);
    }
}

// ---------------------------------------------------------------------------
// Prep 3: edge-padded split-bf16 input planes, FRAGMENT-PACKED
// (16-elem groups permuted so each thread's mma-B quad is contiguous)
// ---------------------------------------------------------------------------
__global__ void xsplit_kernel(const float* __restrict__ att) {
    long long idx = (long long)blockIdx.x * blockDim.x + threadIdx.x;
    if (idx >= (long long)B_N * XPITCH) return;
    int n = (int)(idx / XPITCH);
    int u = (int)(idx - (long long)n * XPITCH);
    int t = u - PAD;
    t = min(max(t, 0), T_LEN - 1);
    float v = att[n * T_LEN + t];
    __nv_bfloat16 h = __float2bfloat16(v);
    float lo = v - __bfloat162float(h);
    __nv_bfloat16 l = __float2bfloat16(lo);
    int g = u >> 4, p = u & 15;
    int np = (p < 8) ? (((p >> 1) << 2) | (p & 1))
                     : ((((p - 8) >> 1) << 2) | 2 | (p & 1));
    size_t dst = (size_t)n * XPITCH + (g << 4) + np;
    gxph[dst] = __bfloat16_as_ushort(h);
    gxpl[dst] = __bfloat16_as_ushort(l);
}

// ---------------------------------------------------------------------------
// Main GEMM: Toeplitz conv via mma.sync m16n8k16 bf16, split-bf16 3-pass.
// cp.async double-buffered x staging; band skip; A-frag chaining; LDS.64 B.
// ---------------------------------------------------------------------------
__global__ void __launch_bounds__(256, 2) gemm_kernel(float* __restrict__ out) {
    extern __shared__ unsigned char smem[];
    unsigned short* wh = (unsigned short*)(smem + WH_OFF);
    unsigned short* wl = (unsigned short*)(smem + WL_OFF);

    const int tid  = threadIdx.x;
    const int warp = tid >> 5;
    const int lane = tid & 31;
    const int Wbase = warp * 64;
    const int r0 = lane >> 2;
    const int c0 = (lane & 3) * 2;
    const int t0 = blockIdx.x * M_CTA;
    const int smin = 4 * warp;
    const int smax = 543 + 4 * warp;

    uint32_t smem_u32;
    asm("{ .reg .u64 t; cvta.to.shared.u64 t, %1; cvt.u32.u64 %0, t; }"
        : "=r"(smem_u32) : "l"(smem));
    const uint32_t xs_u32 = smem_u32 + XS_OFF;

    // stage weights (38.3 KB) once
    for (int i = tid; i < WBUF / 8; i += 256) {
        ((uint4*)wh)[i] = ((const uint4*)g_wh)[i];
        ((uint4*)wl)[i] = ((const uint4*)g_wl)[i];
    }

    // cp.async chunk stage: 2048 x 16B ops, 8 per thread
    auto stage = [&](int c) {
        const int xbase = t0 + c * JT;
        const uint32_t dbase = xs_u32 + (uint32_t)(c & 1) * XBUF;
#pragma unroll
        for (int j = 0; j < 8; j++) {
            int it = tid + 256 * j;
            int plane = it >> 10;
            int r = (it >> 6) & 15;
            int q = it & 63;
            const unsigned short* src =
                (plane ? gxpl : gxph) + (size_t)r * XPITCH + xbase + q * 8;
            uint32_t dst = dbase + (uint32_t)plane * XPLANE
                         + ((uint32_t)r * XSROW + (uint32_t)q * 8) * 2u;
            cp16(dst, src);
        }
        asm volatile("cp.async.commit_group;" ::: "memory");
    };

    float acc[4][2][4];
#pragma unroll
    for (int i = 0; i < 4; i++)
#pragma unroll
        for (int nb = 0; nb < 2; nb++)
#pragma unroll
            for (int q = 0; q < 4; q++) acc[i][nb][q] = 0.f;

    uint32_t Ah[4][3], Al[4][3];
#pragma unroll
    for (int i = 0; i < 4; i++)
#pragma unroll
        for (int q = 0; q < 3; q++) { Ah[i][q] = 0u; Al[i][q] = 0u; }

    stage(0);

    for (int chunk = 0; chunk < NCHK; ++chunk) {
        __syncthreads();                       // prev compute done (buffer reuse safe)
        if (chunk + 1 < NCHK) {
            stage(chunk + 1);
            asm volatile("cp.async.wait_group 1;" ::: "memory");
        } else {
            asm volatile("cp.async.wait_group 0;" ::: "memory");
        }
        __syncthreads();                       // chunk's data visible to all

        const int s0 = chunk * 32;
        int sl_lo = smin - s0; if (sl_lo < 0) sl_lo = 0;
        int sl_hi = smax - s0; if (sl_hi > 31) sl_hi = 31;
        if (sl_lo > sl_hi) continue;

        const unsigned short* xsh =
            (unsigned short*)(smem + XS_OFF + (chunk & 1) * XBUF);
        const unsigned short* xsl = xsh + XPLANE / 2;
        const unsigned short* bh0 = xsh + (lane >> 2) * XSROW + 2 * c0;
        const unsigned short* bh1 = xsh + ((lane >> 2) + 8) * XSROW + 2 * c0;
        const unsigned short* bl0 = xsl + (lane >> 2) * XSROW + 2 * c0;
        const unsigned short* bl1 = xsl + ((lane >> 2) + 8) * XSROW + 2 * c0;

        // chain preload
        uint32_t pAh, pAl;
        {
            const int base0 = WOFF + 16 * (s0 + sl_lo) - Wbase + c0 - r0;
            pAh = pk(wh + base0 - 8);
            pAl = pk(wl + base0 - 8);
        }

#pragma unroll 4
        for (int sl = sl_lo; sl <= sl_hi; ++sl) {
            const int s = s0 + sl;
            const int slot = sl & 3;
            const int base = WOFF + 16 * s - Wbase + c0 - r0;
            Ah[slot][1] = pAh;               Al[slot][1] = pAl;
            Ah[slot][0] = pk(wh + base);     Al[slot][0] = pk(wl + base);
            Ah[slot][2] = pk(wh + base + 8); Al[slot][2] = pk(wl + base + 8);
            pAh = Ah[slot][2];               pAl = Al[slot][2];

            const int jj = 16 * sl;
            uint2 vh0 = *(const uint2*)(bh0 + jj);
            uint2 vh1 = *(const uint2*)(bh1 + jj);
            uint2 vl0 = *(const uint2*)(bl0 + jj);
            uint2 vl1 = *(const uint2*)(bl1 + jj);
            uint32_t bh[2][2] = {{vh0.x, vh0.y}, {vh1.x, vh1.y}};
            uint32_t bl[2][2] = {{vl0.x, vl0.y}, {vl1.x, vl1.y}};

#pragma unroll
            for (int ib = 0; ib < 4; ++ib) {
                const int sig = (sl - ib) & 3;
                mma16816(acc[ib][0], Ah[sig][0], Ah[sig][1], Ah[sig][2], Ah[sig][0], bh[0][0], bh[0][1]);
                mma16816(acc[ib][1], Ah[sig][0], Ah[sig][1], Ah[sig][2], Ah[sig][0], bh[1][0], bh[1][1]);
            }
#pragma unroll
            for (int ib = 0; ib < 4; ++ib) {
                const int sig = (sl - ib) & 3;
                mma16816(acc[ib][0], Ah[sig][0], Ah[sig][1], Ah[sig][2], Ah[sig][0], bl[0][0], bl[0][1]);
                mma16816(acc[ib][1], Ah[sig][0], Ah[sig][1], Ah[sig][2], Ah[sig][0], bl[1][0], bl[1][1]);
            }
#pragma unroll
            for (int ib = 0; ib < 4; ++ib) {
                const int sig = (sl - ib) & 3;
                mma16816(acc[ib][0], Al[sig][0], Al[sig][1], Al[sig][2], Al[sig][0], bh[0][0], bh[0][1]);
                mma16816(acc[ib][1], Al[sig][0], Al[sig][1], Al[sig][2], Al[sig][0], bh[1][0], bh[1][1]);
            }
        }
    }

    // ---- epilogue: transpose through smem, coalesced store ----
    __syncthreads();
    float* smt = (float*)smem;               // [16][520], overlaps weights (done)
#pragma unroll
    for (int ib = 0; ib < 4; ++ib) {
        const int mloc = Wbase + ib * 16 + r0;
#pragma unroll
        for (int nb = 0; nb < 2; ++nb) {
            const int n = c0 + nb * 8;
            smt[n * 520 + mloc]           = acc[ib][nb][0];
            smt[(n + 1) * 520 + mloc]     = acc[ib][nb][1];
            smt[n * 520 + mloc + 8]       = acc[ib][nb][2];
            smt[(n + 1) * 520 + mloc + 8] = acc[ib][nb][3];
        }
    }
    __syncthreads();
    for (int e = tid; e < B_N * M_CTA; e += 256) {
        int n = e >> 9;
        int mloc = e & 511;
        out[n * T_LEN + t0 + mloc] = smt[n * 520 + mloc];
    }
}

// ---------------------------------------------------------------------------
// Mean reduction, MLP, final scale
// ---------------------------------------------------------------------------
__global__ void reduce_kernel(const float* __restrict__ base) {
    __shared__ float red[256];
    const int b = blockIdx.y, c = blockIdx.x;
    const int chunk = T_LEN / NCHUNK;
    const float4* p = (const float4*)(base + b * T_LEN + c * chunk);
    float s = 0.f;
    for (int i = threadIdx.x; i < chunk / 4; i += 256) {
        float4 v = p[i];
        s += (v.x + v.y) + (v.z + v.w);
    }
    red[threadIdx.x] = s; __syncthreads();
    for (int st = 128; st > 0; st >>= 1) {
        if (threadIdx.x < st) red[threadIdx.x] += red[threadIdx.x + st];
        __syncthreads();
    }
    if (threadIdx.x == 0) g_partial[b * NCHUNK + c] = red[0];
}

__global__ void mlp_kernel(const float* __restrict__ meta,
                           const float* __restrict__ W1, const float* __restrict__ b1,
                           const float* __restrict__ W2, const float* __restrict__ b2,
                           const float* __restrict__ W3, const float* __restrict__ b3,
                           const float* __restrict__ cs) {
    const int b = threadIdx.x;
    if (b >= B_N) return;
    float s = 0.f;
    for (int i = 0; i < NCHUNK; ++i) s += g_partial[b * NCHUNK + i];

    float ci[1 + F_META];
    ci[0] = s / (float)T_LEN;
    for (int i = 0; i < F_META; ++i) ci[1 + i] = meta[b * F_META + i];

    float h1[32];
    for (int j = 0; j < 32; ++j) {
        float a = b1[j];
        for (int i = 0; i < 1 + F_META; ++i) a = fmaf(W1[j * (1 + F_META) + i], ci[i], a);
        h1[j] = fmaxf(a, 0.f);
    }
    float h2[16];
    for (int j = 0; j < 16; ++j) {
        float a = b2[j];
        for (int i = 0; i < 32; ++i) a = fmaf(W2[j * 32 + i], h1[i], a);
        h2[j] = fmaxf(a, 0.f);
    }
    float f = b3[0];
    for (int i = 0; i < 16; ++i) f = fmaf(W3[i], h2[i], f);
    g_scale[b] = 1.f + cs[0] * tanhf(f);
}

__global__ void scale_kernel(float* __restrict__ out) {
    int idx = blockIdx.x * blockDim.x + threadIdx.x;
    const int per_b = T_LEN / 4;
    int b = idx / per_b;
    float s = g_scale[b];
    float4* o4 = (float4*)out;
    float4 v = o4[idx];
    v.x *= s; v.y *= s; v.z *= s; v.w *= s;
    o4[idx] = v;
}

// ---------------------------------------------------------------------------
// Launch
// ---------------------------------------------------------------------------
extern "C" void kernel_launch(void* const* d_in, const int* in_sizes, int n_in,
                              void* d_out, int out_size) {
    const float* att  = (const float*)d_in[0];
    const float* meta = (const float*)d_in[1];
    const float* tw   = (const float*)d_in[2];
    const float* W1   = (const float*)d_in[3];
    const float* b1   = (const float*)d_in[4];
    const float* W2   = (const float*)d_in[5];
    const float* b2   = (const float*)d_in[6];
    const float* W3   = (const float*)d_in[7];
    const float* b3   = (const float*)d_in[8];
    const float* cs   = (const float*)d_in[9];
    float* out = (float*)d_out;

    cudaFuncSetAttribute(gemm_kernel, cudaFuncAttributeMaxDynamicSharedMemorySize, SMEM_SZ);

    softmax_flip_kernel<<<1, 256>>>(tw);
    wsplit_kernel<<<1, 256>>>();
    {
        long long tot = (long long)B_N * XPITCH;
        int blocks = (int)((tot + 255) / 256);
        xsplit_kernel<<<blocks, 256>>>(att);
    }
    gemm_kernel<<<GRID_G, 256, SMEM_SZ>>>(out);
    reduce_kernel<<<dim3(NCHUNK, B_N), 256>>>(out);
    mlp_kernel<<<1, 32>>>(meta, W1, b1, W2, b2, W3, b3, cs);
    scale_kernel<<<(B_N * T_LEN / 4 + 255) / 256, 256>>>(out);
}

// round 12
// speedup vs baseline: 1.1649x; 1.1649x over previous
#include <cuda_runtime.h>
#include <cuda_bf16.h>
#include <cstdint>

// ---------------------------------------------------------------------------
// Problem constants
// ---------------------------------------------------------------------------
#define T_LEN   262144
#define B_N     16
#define W_LEN   8640
#define PAD     4320
#define F_META  8
#define NCHUNK  32

// GEMM decomposition
#define UNITS   4096              // 64-row units
#define JT      1024              // taps per x chunk (64 k16-steps)
#define NCHK    10                // chunks per pass (640 steps >= 603+1)
#define XSROW   1040              // x smem pitch elems; 1040*2 % 128 == 32 -> conflict-free LDS.64
#define WBUF    9792              // guarded weight buffer elems
#define WOFF    512
#define XPITCH  271872            // gxp row pitch elems (mult of 16)

// smem byte offsets
#define WH_OFF   0
#define WL_OFF   19584
#define XS_OFF   39168
#define XPLANE   33280            // 16 rows x 1040 elems x 2B
#define XBUF     66560            // hi+lo planes
#define SMEM_SZ  (39168 + 2*66560)   // 172288

// ---------------------------------------------------------------------------
// Device scratch (no cudaMalloc allowed)
// ---------------------------------------------------------------------------
__device__ float g_w[W_LEN];
__device__ __align__(16) unsigned short g_wh[WBUF];
__device__ __align__(16) unsigned short g_wl[WBUF];
__device__ __align__(16) unsigned short gxph[B_N * XPITCH];   // frag-packed
__device__ __align__(16) unsigned short gxpl[B_N * XPITCH];
__device__ float g_partial[B_N * NCHUNK];
__device__ float g_scale[B_N];

// ---------------------------------------------------------------------------
// Helpers
// ---------------------------------------------------------------------------
__device__ __forceinline__ uint32_t pk(const unsigned short* p) {
    return (uint32_t)p[0] | ((uint32_t)p[1] << 16);
}
__device__ __forceinline__ void mma16816(float* d, uint32_t a0, uint32_t a1,
                                         uint32_t a2, uint32_t a3,
                                         uint32_t b0, uint32_t b1) {
    asm volatile(
        "mma.sync.aligned.m16n8k16.row.col.f32.bf16.bf16.f32 "
        "{%0,%1,%2,%3}, {%4,%5,%6,%7}, {%8,%9}, {%0,%1,%2,%3};"
        : "+f"(d[0]), "+f"(d[1]), "+f"(d[2]), "+f"(d[3])
        : "r"(a0), "r"(a1), "r"(a2), "r"(a3), "r"(b0), "r"(b1));
}
__device__ __forceinline__ void cp16(uint32_t dst, const void* src) {
    asm volatile("cp.async.cg.shared.global [%0], [%1], 16;"
                 :: "r"(dst), "l"(src) : "memory");
}

// ---------------------------------------------------------------------------
// Prep 1: softmax over temporal_weights, flipped -> g_w
// ---------------------------------------------------------------------------
__global__ void softmax_flip_kernel(const float* __restrict__ tw) {
    __shared__ float red[256];
    __shared__ float s_max, s_invsum;
    const int tid = threadIdx.x;

    float m = -1e30f;
    for (int i = tid; i < W_LEN; i += 256) m = fmaxf(m, tw[i]);
    red[tid] = m; __syncthreads();
    for (int s = 128; s > 0; s >>= 1) {
        if (tid < s) red[tid] = fmaxf(red[tid], red[tid + s]);
        __syncthreads();
    }
    if (tid == 0) s_max = red[0];
    __syncthreads();
    const float mx = s_max;
    __syncthreads();

    float sum = 0.f;
    for (int i = tid; i < W_LEN; i += 256) sum += expf(tw[i] - mx);
    red[tid] = sum; __syncthreads();
    for (int s = 128; s > 0; s >>= 1) {
        if (tid < s) red[tid] += red[tid + s];
        __syncthreads();
    }
    if (tid == 0) s_invsum = 1.f / red[0];
    __syncthreads();
    const float inv = s_invsum;

    for (int i = tid; i < W_LEN; i += 256)
        g_w[W_LEN - 1 - i] = expf(tw[i] - mx) * inv;
}

// ---------------------------------------------------------------------------
// Prep 2: guarded split-bf16 weight buffer
// ---------------------------------------------------------------------------
__global__ void wsplit_kernel() {
    for (int i = threadIdx.x; i < WBUF; i += 256) {
        int wi = i - WOFF;
        float v = (wi >= 0 && wi < W_LEN) ? g_w[wi] : 0.f;
        __nv_bfloat16 h = __float2bfloat16(v);
        float lo = v - __bfloat162float(h);
        __nv_bfloat16 l = __float2bfloat16(lo);
        g_wh[i] = __bfloat16_as_ushort(h);
        g_wl[i] = __bfloat16_as_ushort(l);
    }
}

// ---------------------------------------------------------------------------
// Prep 3: edge-padded split-bf16 input planes, FRAGMENT-PACKED
// (16-elem groups permuted so each thread's mma-B quad is contiguous)
// ---------------------------------------------------------------------------
__global__ void xsplit_kernel(const float* __restrict__ att) {
    long long idx = (long long)blockIdx.x * blockDim.x + threadIdx.x;
    if (idx >= (long long)B_N * XPITCH) return;
    int n = (int)(idx / XPITCH);
    int u = (int)(idx - (long long)n * XPITCH);
    int t = u - PAD;
    t = min(max(t, 0), T_LEN - 1);
    float v = att[n * T_LEN + t];
    __nv_bfloat16 h = __float2bfloat16(v);
    float lo = v - __bfloat162float(h);
    __nv_bfloat16 l = __float2bfloat16(lo);
    int g = u >> 4, p = u & 15;
    int np = (p < 8) ? (((p >> 1) << 2) | (p & 1))
                     : ((((p - 8) >> 1) << 2) | 2 | (p & 1));
    size_t dst = (size_t)n * XPITCH + (g << 4) + np;
    gxph[dst] = __bfloat16_as_ushort(h);
    gxpl[dst] = __bfloat16_as_ushort(l);
}

// ---------------------------------------------------------------------------
// Main GEMM: persistent uneven-unit CTAs.  One CTA per SM (occ 1, 512 thr,
// 16 warps).  CTA owns U in {26..28} units of 64 rows, split into 2 passes of
// <=16 units (unit w -> warp w).  Per pass: 10 double-buffered cp.async x
// chunks; ring-4 Toeplitz A frags; LDS.64 frag-packed B; 3-pass split-bf16.
// ---------------------------------------------------------------------------
__global__ void __launch_bounds__(512, 1) gemm_kernel(float* __restrict__ out) {
    extern __shared__ unsigned char smem[];
    unsigned short* wh = (unsigned short*)(smem + WH_OFF);
    unsigned short* wl = (unsigned short*)(smem + WL_OFF);

    const int tid  = threadIdx.x;
    const int warp = tid >> 5;
    const int lane = tid & 31;
    const int r0 = lane >> 2;
    const int c0 = (lane & 3) * 2;

    const int G = gridDim.x;
    const int u_start = (int)(((long long)blockIdx.x * UNITS) / G);
    const int u_end   = (int)(((long long)(blockIdx.x + 1) * UNITS) / G);
    const int U = u_end - u_start;

    uint32_t smem_u32;
    asm("{ .reg .u64 t; cvta.to.shared.u64 t, %1; cvt.u32.u64 %0, t; }"
        : "=r"(smem_u32) : "l"(smem));

    // stage weights (38.3 KB) once, used by both passes
    for (int i = tid; i < WBUF / 8; i += 512) {
        ((uint4*)wh)[i] = ((const uint4*)g_wh)[i];
        ((uint4*)wl)[i] = ((const uint4*)g_wl)[i];
    }

    // per-thread cp.async addressing: plane = tid>>8, row = (tid>>4)&15, q0 = tid&15
    const int st_plane = (tid >> 8) & 1;
    const int st_row   = (tid >> 4) & 15;
    const int st_q0    = tid & 15;
    const unsigned short* st_g = (st_plane ? gxpl : gxph)
                               + (size_t)st_row * XPITCH + st_q0 * 8;
    const uint32_t st_dst0 = smem_u32 + XS_OFF + (uint32_t)st_plane * XPLANE
                           + (uint32_t)st_row * (XSROW * 2) + (uint32_t)st_q0 * 16;

    for (int pass = 0; pass < 2; ++pass) {
        const int Ap = min(16, U - 16 * pass);
        if (Ap <= 0) break;
        const int xb = 64 * (u_start + 16 * pass);
        const bool active = (warp < Ap);
        const int smin = active ? 4 * warp : (1 << 29);
        const int smax = active ? 543 + 4 * warp : -1;
        const int Wbase = warp * 64;

        float acc[4][2][4];
#pragma unroll
        for (int i = 0; i < 4; i++)
#pragma unroll
            for (int nb = 0; nb < 2; nb++)
#pragma unroll
                for (int q = 0; q < 4; q++) acc[i][nb][q] = 0.f;
        uint32_t Ah[4][3], Al[4][3];
#pragma unroll
        for (int i = 0; i < 4; i++)
#pragma unroll
            for (int q = 0; q < 3; q++) { Ah[i][q] = 0u; Al[i][q] = 0u; }

        // prologue stage chunk 0
        {
            const unsigned short* src = st_g + xb;
            const uint32_t dst = st_dst0;
#pragma unroll
            for (int j = 0; j < 8; j++) cp16(dst + j * 256u, src + j * 128);
            asm volatile("cp.async.commit_group;" ::: "memory");
        }

        for (int c = 0; c < NCHK; ++c) {
            if (c + 1 < NCHK) {
                const unsigned short* src = st_g + xb + (c + 1) * JT;
                const uint32_t dst = st_dst0 + (uint32_t)((c + 1) & 1) * XBUF;
#pragma unroll
                for (int j = 0; j < 8; j++) cp16(dst + j * 256u, src + j * 128);
                asm volatile("cp.async.commit_group;" ::: "memory");
                asm volatile("cp.async.wait_group 1;" ::: "memory");
            } else {
                asm volatile("cp.async.wait_group 0;" ::: "memory");
            }
            __syncthreads();          // chunk c visible to all

            const int s0 = c * 64;
            int sl_lo = smin - s0; if (sl_lo < 0) sl_lo = 0;
            int sl_hi = smax - s0; if (sl_hi > 63) sl_hi = 63;

            if (sl_lo <= sl_hi) {
                const unsigned short* xsh =
                    (unsigned short*)(smem + XS_OFF + (c & 1) * XBUF);
                const unsigned short* xsl = xsh + XPLANE / 2;
                const unsigned short* bh0 = xsh + (lane >> 2) * XSROW + 2 * c0;
                const unsigned short* bh1 = xsh + ((lane >> 2) + 8) * XSROW + 2 * c0;
                const unsigned short* bl0 = xsl + (lane >> 2) * XSROW + 2 * c0;
                const unsigned short* bl1 = xsl + ((lane >> 2) + 8) * XSROW + 2 * c0;

                uint32_t pAh, pAl;
                {
                    const int base0 = WOFF + 16 * (s0 + sl_lo) - Wbase + c0 - r0;
                    pAh = pk(wh + base0 - 8);
                    pAl = pk(wl + base0 - 8);
                }

#pragma unroll 4
                for (int sl = sl_lo; sl <= sl_hi; ++sl) {
                    const int s = s0 + sl;
                    const int slot = sl & 3;
                    const int base = WOFF + 16 * s - Wbase + c0 - r0;
                    Ah[slot][1] = pAh;               Al[slot][1] = pAl;
                    Ah[slot][0] = pk(wh + base);     Al[slot][0] = pk(wl + base);
                    Ah[slot][2] = pk(wh + base + 8); Al[slot][2] = pk(wl + base + 8);
                    pAh = Ah[slot][2];               pAl = Al[slot][2];

                    const int jj = 16 * sl;
                    uint2 vh0 = *(const uint2*)(bh0 + jj);
                    uint2 vh1 = *(const uint2*)(bh1 + jj);
                    uint2 vl0 = *(const uint2*)(bl0 + jj);
                    uint2 vl1 = *(const uint2*)(bl1 + jj);
                    uint32_t bh[2][2] = {{vh0.x, vh0.y}, {vh1.x, vh1.y}};
                    uint32_t bl[2][2] = {{vl0.x, vl0.y}, {vl1.x, vl1.y}};

#pragma unroll
                    for (int ib = 0; ib < 4; ++ib) {
                        const int sig = (sl - ib) & 3;
                        mma16816(acc[ib][0], Ah[sig][0], Ah[sig][1], Ah[sig][2], Ah[sig][0], bh[0][0], bh[0][1]);
                        mma16816(acc[ib][1], Ah[sig][0], Ah[sig][1], Ah[sig][2], Ah[sig][0], bh[1][0], bh[1][1]);
                    }
#pragma unroll
                    for (int ib = 0; ib < 4; ++ib) {
                        const int sig = (sl - ib) & 3;
                        mma16816(acc[ib][0], Ah[sig][0], Ah[sig][1], Ah[sig][2], Ah[sig][0], bl[0][0], bl[0][1]);
                        mma16816(acc[ib][1], Ah[sig][0], Ah[sig][1], Ah[sig][2], Ah[sig][0], bl[1][0], bl[1][1]);
                    }
#pragma unroll
                    for (int ib = 0; ib < 4; ++ib) {
                        const int sig = (sl - ib) & 3;
                        mma16816(acc[ib][0], Al[sig][0], Al[sig][1], Al[sig][2], Al[sig][0], bh[0][0], bh[0][1]);
                        mma16816(acc[ib][1], Al[sig][0], Al[sig][1], Al[sig][2], Al[sig][0], bh[1][0], bh[1][1]);
                    }
                }
            }
            __syncthreads();          // buffer (c+1)&1 free for restage
        }

        // ---- per-pass epilogue: transpose via smt in x-buffer region ----
        float* smt = (float*)(smem + XS_OFF);      // 16 x 1040 floats fits XBUF
        const int rows = 64 * Ap;
        if (active) {
#pragma unroll
            for (int ib = 0; ib < 4; ++ib) {
                const int mloc = Wbase + ib * 16 + r0;
#pragma unroll
                for (int nb = 0; nb < 2; ++nb) {
                    const int n = c0 + nb * 8;
                    smt[n * XSROW + mloc]           = acc[ib][nb][0];
                    smt[(n + 1) * XSROW + mloc]     = acc[ib][nb][1];
                    smt[n * XSROW + mloc + 8]       = acc[ib][nb][2];
                    smt[(n + 1) * XSROW + mloc + 8] = acc[ib][nb][3];
                }
            }
        }
        __syncthreads();
#pragma unroll 1
        for (int n = 0; n < B_N; ++n)
            for (int r = tid; r < rows; r += 512)
                out[n * T_LEN + xb + r] = smt[n * XSROW + r];
        __syncthreads();              // smt dead before next pass stages x
    }
}

// ---------------------------------------------------------------------------
// Mean reduction, MLP, final scale
// ---------------------------------------------------------------------------
__global__ void reduce_kernel(const float* __restrict__ base) {
    __shared__ float red[256];
    const int b = blockIdx.y, c = blockIdx.x;
    const int chunk = T_LEN / NCHUNK;
    const float4* p = (const float4*)(base + b * T_LEN + c * chunk);
    float s = 0.f;
    for (int i = threadIdx.x; i < chunk / 4; i += 256) {
        float4 v = p[i];
        s += (v.x + v.y) + (v.z + v.w);
    }
    red[threadIdx.x] = s; __syncthreads();
    for (int st = 128; st > 0; st >>= 1) {
        if (threadIdx.x < st) red[threadIdx.x] += red[threadIdx.x + st];
        __syncthreads();
    }
    if (threadIdx.x == 0) g_partial[b * NCHUNK + c] = red[0];
}

__global__ void mlp_kernel(const float* __restrict__ meta,
                           const float* __restrict__ W1, const float* __restrict__ b1,
                           const float* __restrict__ W2, const float* __restrict__ b2,
                           const float* __restrict__ W3, const float* __restrict__ b3,
                           const float* __restrict__ cs) {
    const int b = threadIdx.x;
    if (b >= B_N) return;
    float s = 0.f;
    for (int i = 0; i < NCHUNK; ++i) s += g_partial[b * NCHUNK + i];

    float ci[1 + F_META];
    ci[0] = s / (float)T_LEN;
    for (int i = 0; i < F_META; ++i) ci[1 + i] = meta[b * F_META + i];

    float h1[32];
    for (int j = 0; j < 32; ++j) {
        float a = b1[j];
        for (int i = 0; i < 1 + F_META; ++i) a = fmaf(W1[j * (1 + F_META) + i], ci[i], a);
        h1[j] = fmaxf(a, 0.f);
    }
    float h2[16];
    for (int j = 0; j < 16; ++j) {
        float a = b2[j];
        for (int i = 0; i < 32; ++i) a = fmaf(W2[j * 32 + i], h1[i], a);
        h2[j] = fmaxf(a, 0.f);
    }
    float f = b3[0];
    for (int i = 0; i < 16; ++i) f = fmaf(W3[i], h2[i], f);
    g_scale[b] = 1.f + cs[0] * tanhf(f);
}

__global__ void scale_kernel(float* __restrict__ out) {
    int idx = blockIdx.x * blockDim.x + threadIdx.x;
    const int per_b = T_LEN / 4;
    int b = idx / per_b;
    float s = g_scale[b];
    float4* o4 = (float4*)out;
    float4 v = o4[idx];
    v.x *= s; v.y *= s; v.z *= s; v.w *= s;
    o4[idx] = v;
}

// ---------------------------------------------------------------------------
// Launch
// ---------------------------------------------------------------------------
extern "C" void kernel_launch(void* const* d_in, const int* in_sizes, int n_in,
                              void* d_out, int out_size) {
    const float* att  = (const float*)d_in[0];
    const float* meta = (const float*)d_in[1];
    const float* tw   = (const float*)d_in[2];
    const float* W1   = (const float*)d_in[3];
    const float* b1   = (const float*)d_in[4];
    const float* W2   = (const float*)d_in[5];
    const float* b2   = (const float*)d_in[6];
    const float* W3   = (const float*)d_in[7];
    const float* b3   = (const float*)d_in[8];
    const float* cs   = (const float*)d_in[9];
    float* out = (float*)d_out;

    int nsm = 148;
    cudaDeviceGetAttribute(&nsm, cudaDevAttrMultiProcessorCount, 0);
    if (nsm <= 0 || nsm > 1024) nsm = 148;

    cudaFuncSetAttribute(gemm_kernel, cudaFuncAttributeMaxDynamicSharedMemorySize, SMEM_SZ);

    softmax_flip_kernel<<<1, 256>>>(tw);
    wsplit_kernel<<<1, 256>>>();
    {
        long long tot = (long long)B_N * XPITCH;
        int blocks = (int)((tot + 255) / 256);
        xsplit_kernel<<<blocks, 256>>>(att);
    }
    gemm_kernel<<<nsm, 512, SMEM_SZ>>>(out);
    reduce_kernel<<<dim3(NCHUNK, B_N), 256>>>(out);
    mlp_kernel<<<1, 32>>>(meta, W1, b1, W2, b2, W3, b3, cs);
    scale_kernel<<<(B_N * T_LEN / 4 + 255) / 256, 256>>>(out);
}